// round 9
// baseline (speedup 1.0000x reference)
#include <cuda_runtime.h>

// Occupancy connectivity loss over a 385^3 fp32 grid, C order:
//   f = x*385^2 + y*385 + z
// Block = 8 warps = 8 consecutive y-rows of a 128-wide z segment (+1 halo
// column), marching over a 64-plane x chunk. 2-deep prefetch: registers hold
// planes x (v) and x+1 (n); the LDG for x+2 (m) is issued each iteration and
// not consumed until the next -> full-iteration latency slack.
//   x-diff: |n - v| (both register-resident)
//   z-diff: own smem row at [idx+1] (conflict-free scalar LDS)
//   y-diff: neighbor warp's smem row
// Rows loaded 8, owned 7. Double-buffered smem. 7 blocks/SM.

#define ROW    385u
#define PLANE  148225u
#define WPB    8u
#define OWN    7u
#define NYG    55u
#define XC     6u
#define NZSEG  3u
#define NBLOCKS (NZSEG * NYG * XC)   // 990

__device__ double   g_part[NBLOCKS];
__device__ unsigned g_count = 0;

__global__ void __launch_bounds__(256, 7)
occ_main(const float* __restrict__ occ, float* __restrict__ out) {
    const unsigned wid  = threadIdx.x >> 5;
    const unsigned lane = threadIdx.x & 31u;
    const bool     l31  = (lane == 31u);

    const unsigned zseg = blockIdx.x % NZSEG;
    const unsigned rest = blockIdx.x / NZSEG;
    const unsigned xc   = rest % XC;
    const unsigned g    = rest / XC;

    const unsigned zb = zseg * 128u;
    const unsigned y  = g * OWN + wid;
    const bool rowload = (y <= 384u);
    const bool rowown  = (wid < OWN);
    const bool ypair   = rowown && (y < 384u);
    const bool hseg31  = (zseg == NZSEG - 1u) && l31;  // z=384 column diffs

    const unsigned as = 64u * xc;            // chunk planes [as, as+64]
    const int  mid    = 64;                  // x-pairs per chunk
    const bool lastc  = (xc == XC - 1u);

    __shared__ float sm[2][WPB][132];

    const float* p = occ + (size_t)y * ROW + zb + lane + (size_t)as * PLANE;

    float s0 = 0.f, s1 = 0.f;
    float v0=0.f,v1=0.f,v2=0.f,v3=0.f,hc=0.f;   // plane x
    float n0=0.f,n1=0.f,n2=0.f,n3=0.f,hn=0.f;   // plane x+1

    if (rowload) {
        v0=__ldg(p); v1=__ldg(p+32); v2=__ldg(p+64); v3=__ldg(p+96);
        if (l31) hc=__ldg(p+97);
        p += PLANE;
        n0=__ldg(p); n1=__ldg(p+32); n2=__ldg(p+64); n3=__ldg(p+96);
        if (l31) hn=__ldg(p+97);
        p += PLANE;                               // points at plane x+2
    }

    unsigned buf = 0u;
    #pragma unroll 2
    for (int i = 0; i < mid; ++i) {
        // publish plane x (regs 2 iterations old)
        float m0=0.f,m1=0.f,m2=0.f,m3=0.f,hm=0.f;
        if (rowload) {
            float* r = sm[buf][wid];
            r[lane]=v0; r[lane+32u]=v1; r[lane+64u]=v2; r[lane+96u]=v3;
            if (l31) r[128]=hc;
            // prefetch plane x+2 (guard the one-past-chunk overrun at x=384)
            if (i + 2 <= mid || !lastc) {
                m0=__ldg(p); m1=__ldg(p+32); m2=__ldg(p+64); m3=__ldg(p+96);
                if (l31) hm=__ldg(p+97);
                p += PLANE;
            }
        }
        __syncthreads();
        if (rowown) {
            const float* r = sm[buf][wid];
            // z-diffs for plane x (incl. halo column at r[lane+97])
            s0 += fabsf(r[lane+1u]  - v0) + fabsf(r[lane+33u] - v1);
            s1 += fabsf(r[lane+65u] - v2) + fabsf(r[lane+97u] - v3);
            if (ypair) {
                const float* q = sm[buf][wid+1u];
                s0 += fabsf(q[lane]      - v0) + fabsf(q[lane+32u] - v1);
                s1 += fabsf(q[lane+64u]  - v2) + fabsf(q[lane+96u] - v3);
                if (hseg31) s0 += fabsf(q[128] - hc);
            }
            // x-diffs for pair (x, x+1): both register-resident
            s0 += fabsf(n0 - v0) + fabsf(n1 - v1);
            s1 += fabsf(n2 - v2) + fabsf(n3 - v3);
            if (hseg31) s0 += fabsf(hn - hc);
        }
        v0=n0; v1=n1; v2=n2; v3=n3; hc=hn;
        n0=m0; n1=m1; n2=m2; n3=m3; hn=hm;
        buf ^= 1u;
    }

    // ---- final plane of the grid (x = 384): z/y diffs, last chunk only ----
    if (lastc) {
        if (rowload) {
            float* r = sm[buf][wid];
            r[lane]=v0; r[lane+32u]=v1; r[lane+64u]=v2; r[lane+96u]=v3;
            if (l31) r[128]=hc;
        }
        __syncthreads();
        if (rowown) {
            const float* r = sm[buf][wid];
            s0 += fabsf(r[lane+1u]  - v0) + fabsf(r[lane+33u] - v1);
            s1 += fabsf(r[lane+65u] - v2) + fabsf(r[lane+97u] - v3);
            if (ypair) {
                const float* q = sm[buf][wid+1u];
                s0 += fabsf(q[lane]      - v0) + fabsf(q[lane+32u] - v1);
                s1 += fabsf(q[lane+64u]  - v2) + fabsf(q[lane+96u] - v3);
                if (hseg31) s0 += fabsf(q[128] - hc);
            }
        }
    }

    // ---- block reduction ----
    float s = s0 + s1;
    #pragma unroll
    for (int o = 16; o > 0; o >>= 1)
        s += __shfl_down_sync(0xffffffffu, s, o);

    __shared__ float    ws[WPB];
    __shared__ unsigned islast_s;
    if (lane == 0u) ws[wid] = s;
    __syncthreads();
    if (threadIdx.x == 0u) {
        float t = 0.f;
        #pragma unroll
        for (unsigned i = 0; i < WPB; ++i) t += ws[i];
        g_part[blockIdx.x] = (double)t;
        __threadfence();
        unsigned old = atomicAdd(&g_count, 1u);
        islast_s = (old == NBLOCKS - 1u) ? 1u : 0u;
    }
    __syncthreads();

    // ---- last block folds partials (single launch total) ----
    if (islast_s) {
        double d = 0.0;
        for (unsigned i = threadIdx.x; i < NBLOCKS; i += 256u)
            d += g_part[i];
        __shared__ double dsm[256];
        dsm[threadIdx.x] = d;
        __syncthreads();
        #pragma unroll
        for (int st = 128; st > 0; st >>= 1) {
            if ((int)threadIdx.x < st) dsm[threadIdx.x] += dsm[threadIdx.x + st];
            __syncthreads();
        }
        if (threadIdx.x == 0u) {
            out[0] = (float)dsm[0];
            g_count = 0u;   // reset for next graph replay
        }
    }
}

extern "C" void kernel_launch(void* const* d_in, const int* in_sizes, int n_in,
                              void* d_out, int out_size) {
    const float* occ = (const float*)d_in[0];
    float* out = (float*)d_out;
    occ_main<<<NBLOCKS, 256>>>(occ, out);
}